// round 10
// baseline (speedup 1.0000x reference)
#include <cuda_runtime.h>
#include <math.h>

#define BATCH 64
#define MOLA  50
#define PROA  500
#define HID   32
#define HEADS 8
#define NMOL  (BATCH * MOLA)          // 3200
#define NPRO  (BATCH * PROA)          // 32000
#define NPAIR ((size_t)NMOL * PROA)   // 1,600,000

#define FTHREADS 512
#define NW       (FTHREADS / 32)      // 16 warps
#define CHUNK    25                   // mol atoms per block
#define NCHUNK   (MOLA / CHUNK)       // 2

// Scratch (allocation-free rule: __device__ globals)
// Per-(mol atom, warp, head-half) partial sums of mu. 3200*16*8 floats = 1.6 MB.
__device__ float g_ypart[(size_t)NMOL * NW * HEADS];

// ---------------------------------------------------------------------------
// Fused kernel: block = (complex b, chunk of 25 mol atoms). 128 blocks x 512.
//  Phase 1: compute the complex's P-table (pro*spat @ W[32:64]) directly into
//           smem; compute the chunk's 25 A-terms (mol @ W[0:32] + bias) into smem.
//  Phase 2: stream 25 x 1000 float4 work items; work item v = q*2 + sel
//           (pair q, head-half sel=tid&1) -> 16B lane stride, dense STG.128,
//           streaming stores. Branchless ELU:
//             mu    = max(x+1.0, exp(min(x,0)))
//             sigma = max(x+1.1, exp(min(x,0))+0.1)
//  Reduction: same-parity warp butterfly (16,8,4,2); lanes 0/1 write per-warp
//  float4 partials to g_ypart. NO block barriers in the main loop.
// ---------------------------------------------------------------------------
__global__ __launch_bounds__(FTHREADS)
void fused_kernel(const float* __restrict__ mol_feats,
                  const float* __restrict__ pro_feats,
                  const float* __restrict__ spat,
                  const float* __restrict__ Wsig,
                  const float* __restrict__ bsig,
                  const float* __restrict__ Wmu,
                  const float* __restrict__ bmu,
                  float* __restrict__ out_mu, float* __restrict__ out_sig)
{
    __shared__ float4 sPmu[PROA * 2];          // 16 KB  (P-table, mu)
    __shared__ float4 sPsg[PROA * 2];          // 16 KB  (P-table, sigma)
    __shared__ float4 sWmu4[2 * HID * 2];      // 2 KB   [k][half]
    __shared__ float4 sWsg4[2 * HID * 2];      // 2 KB
    __shared__ float4 sAmu[CHUNK * 2];         // 800 B  [mol-local][half]
    __shared__ float4 sAsg[CHUNK * 2];         // 800 B

    const int b     = blockIdx.x >> 1;         // complex
    const int chunk = blockIdx.x & 1;          // which 25 mol atoms
    const int tid   = threadIdx.x;
    const int sel   = tid & 1;
    const int wid   = tid >> 5;
    const int lid   = tid & 31;

    // --- weights to smem (W is [64][8] row-major = float4[k*2+half] exactly) ---
    for (int i = tid; i < 2 * HID * 2; i += FTHREADS) {
        sWmu4[i] = ((const float4*)Wmu)[i];
        sWsg4[i] = ((const float4*)Wsig)[i];
    }
    __syncthreads();   // weights ready

    // --- Phase 1a: P-table. 1000 row-halves over 512 threads (2 iters). ---
    {
        const size_t probase = (size_t)b * PROA;
        for (int v = tid; v < PROA * 2; v += FTHREADS) {
            const int row  = v >> 1;
            const int half = v & 1;
            const float4* fp = (const float4*)(pro_feats + (probase + row) * HID);
            const float4* sp = (const float4*)(spat      + (probase + row) * HID);
            float m0 = 0.f, m1 = 0.f, m2 = 0.f, m3 = 0.f;
            float c0 = 0.f, c1 = 0.f, c2 = 0.f, c3 = 0.f;
            #pragma unroll
            for (int c = 0; c < HID / 4; c++) {
                float4 f4 = fp[c];
                const float4 s4 = sp[c];
                f4.x *= s4.x; f4.y *= s4.y; f4.z *= s4.z; f4.w *= s4.w;
                const float fv[4] = { f4.x, f4.y, f4.z, f4.w };
                #pragma unroll
                for (int e = 0; e < 4; e++) {
                    const int k = c * 4 + e;
                    const float4 wm = sWmu4[(HID + k) * 2 + half];
                    const float4 ws = sWsg4[(HID + k) * 2 + half];
                    m0 = fmaf(fv[e], wm.x, m0); m1 = fmaf(fv[e], wm.y, m1);
                    m2 = fmaf(fv[e], wm.z, m2); m3 = fmaf(fv[e], wm.w, m3);
                    c0 = fmaf(fv[e], ws.x, c0); c1 = fmaf(fv[e], ws.y, c1);
                    c2 = fmaf(fv[e], ws.z, c2); c3 = fmaf(fv[e], ws.w, c3);
                }
            }
            sPmu[v] = make_float4(m0, m1, m2, m3);
            sPsg[v] = make_float4(c0, c1, c2, c3);
        }
    }

    // --- Phase 1b: A-terms for this chunk's 25 mol atoms (50 row-halves). ---
    if (tid < CHUNK * 2) {
        const int ml   = tid >> 1;
        const int half = tid & 1;
        const int m    = b * MOLA + chunk * CHUNK + ml;
        const float4 bm = ((const float4*)bmu)[half];
        const float4 bs = ((const float4*)bsig)[half];
        float m0 = bm.x, m1 = bm.y, m2 = bm.z, m3 = bm.w;
        float c0 = bs.x, c1 = bs.y, c2 = bs.z, c3 = bs.w;
        const float4* fp = (const float4*)(mol_feats + (size_t)m * HID);
        #pragma unroll
        for (int c = 0; c < HID / 4; c++) {
            const float4 f4 = fp[c];
            const float fv[4] = { f4.x, f4.y, f4.z, f4.w };
            #pragma unroll
            for (int e = 0; e < 4; e++) {
                const int k = c * 4 + e;
                const float4 wm = sWmu4[k * 2 + half];
                const float4 ws = sWsg4[k * 2 + half];
                m0 = fmaf(fv[e], wm.x, m0); m1 = fmaf(fv[e], wm.y, m1);
                m2 = fmaf(fv[e], wm.z, m2); m3 = fmaf(fv[e], wm.w, m3);
                c0 = fmaf(fv[e], ws.x, c0); c1 = fmaf(fv[e], ws.y, c1);
                c2 = fmaf(fv[e], ws.z, c2); c3 = fmaf(fv[e], ws.w, c3);
            }
        }
        sAmu[tid] = make_float4(m0, m1, m2, m3);
        sAsg[tid] = make_float4(c0, c1, c2, c3);
    }
    __syncthreads();   // P-table + A-terms ready

    // --- Phase 2: stream the pairs. No block barriers from here on. ---
    #pragma unroll 1
    for (int ma = 0; ma < CHUNK; ma++) {
        const int m = b * MOLA + chunk * CHUNK + ma;
        const float4 a4 = sAmu[ma * 2 + sel];
        const float4 s4 = sAsg[ma * 2 + sel];

        float acc0 = 0.f, acc1 = 0.f, acc2 = 0.f, acc3 = 0.f;

        const size_t obase = (size_t)m * (PROA * 2);   // float4 index
        float4* __restrict__ om = (float4*)out_mu  + obase;
        float4* __restrict__ os = (float4*)out_sig + obase;

        #pragma unroll
        for (int it = 0; it < 2; it++) {
            const int v = it * FTHREADS + tid;
            if (v < PROA * 2) {
                const float4 pm = sPmu[v];
                const float4 ps = sPsg[v];

                const float xm0 = a4.x + pm.x, xm1 = a4.y + pm.y;
                const float xm2 = a4.z + pm.z, xm3 = a4.w + pm.w;
                const float xs0 = s4.x + ps.x, xs1 = s4.y + ps.y;
                const float xs2 = s4.z + ps.z, xs3 = s4.w + ps.w;

                const float mu0 = fmaxf(xm0 + 1.0f, __expf(fminf(xm0, 0.f)));
                const float mu1 = fmaxf(xm1 + 1.0f, __expf(fminf(xm1, 0.f)));
                const float mu2 = fmaxf(xm2 + 1.0f, __expf(fminf(xm2, 0.f)));
                const float mu3 = fmaxf(xm3 + 1.0f, __expf(fminf(xm3, 0.f)));
                const float sg0 = fmaxf(xs0 + 1.1f, __expf(fminf(xs0, 0.f)) + 0.1f);
                const float sg1 = fmaxf(xs1 + 1.1f, __expf(fminf(xs1, 0.f)) + 0.1f);
                const float sg2 = fmaxf(xs2 + 1.1f, __expf(fminf(xs2, 0.f)) + 0.1f);
                const float sg3 = fmaxf(xs3 + 1.1f, __expf(fminf(xs3, 0.f)) + 0.1f);

                acc0 += mu0; acc1 += mu1; acc2 += mu2; acc3 += mu3;

                __stcs(om + v, make_float4(mu0, mu1, mu2, mu3));
                __stcs(os + v, make_float4(sg0, sg1, sg2, sg3));
            }
        }

        // Same-parity butterfly: lane 0 -> heads 0-3 partial, lane 1 -> heads 4-7.
        #pragma unroll
        for (int s = 16; s > 1; s >>= 1) {
            acc0 += __shfl_xor_sync(0xFFFFFFFFu, acc0, s);
            acc1 += __shfl_xor_sync(0xFFFFFFFFu, acc1, s);
            acc2 += __shfl_xor_sync(0xFFFFFFFFu, acc2, s);
            acc3 += __shfl_xor_sync(0xFFFFFFFFu, acc3, s);
        }
        if (lid < 2) {
            // scalar layout: g_ypart[((m*NW + wid)*2 + lid)*4 + comp]
            ((float4*)g_ypart)[((size_t)m * NW + wid) * 2 + lid] =
                make_float4(acc0, acc1, acc2, acc3);
        }
    }
}

// ---------------------------------------------------------------------------
// Final kernel: one block per complex. Reduce g_ypart (50 mol atoms x 16 warps
// x 8 heads) deterministically, then the 2-layer MLP head.
//   y[b] = elu((0.001 * sum) @ W1 + b1) @ W2 + b2
// ---------------------------------------------------------------------------
__global__ __launch_bounds__(256)
void final_kernel(const float* __restrict__ W1, const float* __restrict__ b1,
                  const float* __restrict__ W2, const float* __restrict__ b2,
                  float* __restrict__ out_y)
{
    __shared__ float sred[32][HEADS + 1];
    __shared__ float sy[HEADS];

    const int b   = blockIdx.x;
    const int tid = threadIdx.x;
    const int h   = tid & 7;
    const int s   = tid >> 3;            // 32 slices

    // 800 (m,w) pairs split into 32 slices of 25, fixed order -> deterministic.
    float acc = 0.f;
    #pragma unroll 5
    for (int q = 0; q < 25; q++) {
        const int p = s * 25 + q;        // p in [0,800)
        const int m = p >> 4;            // mol-local 0..49
        const int w = p & 15;            // warp 0..15
        acc += g_ypart[(((size_t)(b * MOLA + m)) * NW + w) * HEADS + h];
    }
    sred[s][h] = acc;
    __syncthreads();

    if (tid < HEADS) {
        float t = 0.f;
        #pragma unroll
        for (int k = 0; k < 32; k++) t += sred[k][tid];
        sy[tid] = t * 0.001f;
    }
    __syncthreads();

    if (tid == 0) {
        float y[HEADS];
        #pragma unroll
        for (int hh = 0; hh < HEADS; hh++) y[hh] = sy[hh];
        float outv = b2[0];
        #pragma unroll
        for (int j = 0; j < 2 * HEADS; j++) {
            float t = b1[j];
            #pragma unroll
            for (int hh = 0; hh < HEADS; hh++)
                t = fmaf(y[hh], W1[hh * (2 * HEADS) + j], t);
            t = (t > 0.f) ? t : expm1f(t);   // plain elu, keep precise
            outv = fmaf(t, W2[j], outv);
        }
        out_y[b] = outv;
    }
}

// ---------------------------------------------------------------------------
// Launch. Inputs (metadata order): mol_feats, pro_feats, spatial_feats,
// W_sigma, b_sigma, W_mu, b_mu, W1, b1, W2, b2, mol_index, pro_index, mol_batch.
// Indices are fully structured -> computed arithmetically, never read.
// Output: [mu (P*8) | sigma (P*8) | y (64)] float32.
// ---------------------------------------------------------------------------
extern "C" void kernel_launch(void* const* d_in, const int* in_sizes, int n_in,
                              void* d_out, int out_size)
{
    const float* mol_feats = (const float*)d_in[0];
    const float* pro_feats = (const float*)d_in[1];
    const float* spat      = (const float*)d_in[2];
    const float* Wsig      = (const float*)d_in[3];
    const float* bsig      = (const float*)d_in[4];
    const float* Wmu       = (const float*)d_in[5];
    const float* bmu       = (const float*)d_in[6];
    const float* W1        = (const float*)d_in[7];
    const float* b1        = (const float*)d_in[8];
    const float* W2        = (const float*)d_in[9];
    const float* b2        = (const float*)d_in[10];

    float* out_mu  = (float*)d_out;
    float* out_sig = out_mu + NPAIR * HEADS;
    float* out_y   = out_mu + 2 * NPAIR * HEADS;

    fused_kernel<<<BATCH * NCHUNK, FTHREADS>>>(mol_feats, pro_feats, spat,
                                               Wsig, bsig, Wmu, bmu,
                                               out_mu, out_sig);
    final_kernel<<<BATCH, 256>>>(W1, b1, W2, b2, out_y);
}

// round 11
// speedup vs baseline: 1.7691x; 1.7691x over previous
#include <cuda_runtime.h>
#include <math.h>

#define BATCH 64
#define MOLA  50
#define PROA  500
#define HID   32
#define HEADS 8
#define NMOL  (BATCH * MOLA)          // 3200
#define NPRO  (BATCH * PROA)          // 32000
#define NPAIR ((size_t)NMOL * PROA)   // 1,600,000

// Scratch (allocation-free rule: __device__ globals)
__device__ float g_Amu [NMOL * HEADS];
__device__ float g_Asig[NMOL * HEADS];
__device__ float g_Pmu [NPRO * HEADS];
__device__ float g_Psig[NPRO * HEADS];
__device__ float g_ymol[NMOL * HEADS];

// ---------------------------------------------------------------------------
// Kernel 1: per-atom projections, 4-way k-split for latency.
// One thread per (row, head-half, k-quarter): 281,600 threads (1100 full
// blocks of 256 — no partial block, warp-uniform mol/pro).
//   q = t&3 (k-quarter: features [q*8, q*8+8)), sel = (t>>2)&1 (head half),
//   r = t>>3 (row).
// Each thread: 2 float4 feature loads (4 for pro: feats+spat), 64 FMAs,
// then butterfly over q (shfl_xor 1,2); lane q==0 adds bias and stores the
// two float4 results. 4x the warps and 4x shorter dep chains than R9.
// ---------------------------------------------------------------------------
__global__ __launch_bounds__(256)
void proj_kernel(const float* __restrict__ mol_feats,
                 const float* __restrict__ pro_feats,
                 const float* __restrict__ spat,
                 const float* __restrict__ Wsig,
                 const float* __restrict__ bsig,
                 const float* __restrict__ Wmu,
                 const float* __restrict__ bmu)
{
    __shared__ float4 sWmu4[2 * HID * 2];    // [k][half] float4 layout, 1 KB
    __shared__ float4 sWsg4[2 * HID * 2];
    for (int i = threadIdx.x; i < 2 * HID * 2; i += blockDim.x) {
        sWmu4[i] = ((const float4*)Wmu)[i];
        sWsg4[i] = ((const float4*)Wsig)[i];
    }
    __syncthreads();

    const int t   = blockIdx.x * blockDim.x + threadIdx.x;
    const int q   = t & 3;                   // k-quarter
    const int sel = (t >> 2) & 1;            // head half
    const int r   = t >> 3;                  // row
    if (r >= NMOL + NPRO) return;            // never taken (grid exact)

    const bool isMol = (r < NMOL);
    const int  j     = isMol ? r : (r - NMOL);

    float am0 = 0.f, am1 = 0.f, am2 = 0.f, am3 = 0.f;
    float as0 = 0.f, as1 = 0.f, as2 = 0.f, as3 = 0.f;

    const int wbase = isMol ? 0 : HID;       // weight k-offset (rows 32..63 for pro)

    const float4* fsrc = isMol ? (const float4*)(mol_feats + (size_t)r * HID)
                               : (const float4*)(pro_feats + (size_t)j * HID);
    const float4* ssrc = isMol ? (const float4*)nullptr
                               : (const float4*)(spat + (size_t)j * HID);

    #pragma unroll
    for (int c2 = 0; c2 < 2; c2++) {
        const int c = q * 2 + c2;
        float4 f4 = fsrc[c];
        if (!isMol) {
            const float4 s4 = ssrc[c];
            f4.x *= s4.x; f4.y *= s4.y; f4.z *= s4.z; f4.w *= s4.w;
        }
        const float fv[4] = { f4.x, f4.y, f4.z, f4.w };
        #pragma unroll
        for (int e = 0; e < 4; e++) {
            const int k = c * 4 + e;
            const float4 wm = sWmu4[(wbase + k) * 2 + sel];
            const float4 ws = sWsg4[(wbase + k) * 2 + sel];
            am0 = fmaf(fv[e], wm.x, am0); am1 = fmaf(fv[e], wm.y, am1);
            am2 = fmaf(fv[e], wm.z, am2); am3 = fmaf(fv[e], wm.w, am3);
            as0 = fmaf(fv[e], ws.x, as0); as1 = fmaf(fv[e], ws.y, as1);
            as2 = fmaf(fv[e], ws.z, as2); as3 = fmaf(fv[e], ws.w, as3);
        }
    }

    // Combine the 4 k-quarters (lanes differing in bits 0-1).
    #pragma unroll
    for (int s = 1; s <= 2; s <<= 1) {
        am0 += __shfl_xor_sync(0xFFFFFFFFu, am0, s);
        am1 += __shfl_xor_sync(0xFFFFFFFFu, am1, s);
        am2 += __shfl_xor_sync(0xFFFFFFFFu, am2, s);
        am3 += __shfl_xor_sync(0xFFFFFFFFu, am3, s);
        as0 += __shfl_xor_sync(0xFFFFFFFFu, as0, s);
        as1 += __shfl_xor_sync(0xFFFFFFFFu, as1, s);
        as2 += __shfl_xor_sync(0xFFFFFFFFu, as2, s);
        as3 += __shfl_xor_sync(0xFFFFFFFFu, as3, s);
    }

    if (q == 0) {
        if (isMol) {
            const float4 bm = ((const float4*)bmu)[sel];
            const float4 bs = ((const float4*)bsig)[sel];
            ((float4*)g_Amu )[(size_t)r * 2 + sel] =
                make_float4(am0 + bm.x, am1 + bm.y, am2 + bm.z, am3 + bm.w);
            ((float4*)g_Asig)[(size_t)r * 2 + sel] =
                make_float4(as0 + bs.x, as1 + bs.y, as2 + bs.z, as3 + bs.w);
        } else {
            ((float4*)g_Pmu )[(size_t)j * 2 + sel] = make_float4(am0, am1, am2, am3);
            ((float4*)g_Psig)[(size_t)j * 2 + sel] = make_float4(as0, as1, as2, as3);
        }
    }
}

// ---------------------------------------------------------------------------
// Kernel 2 (R9 winner, unchanged structure): per-pair mu/sigma + per-mol-atom
// sum of mu. Block = (complex b, chunk of 5 mol atoms): 640 blocks x 256.
// Work item v = q*2 + sel: 16B lane stride -> fully dense STG.128, streaming.
// P-table AND A-terms staged in smem once per block.
// Branchless ELU: mu = max(x+1, exp(min(x,0))), sg = max(x+1.1, exp(min(x,0))+0.1)
// ---------------------------------------------------------------------------
#define CHUNK_MOL 5
#define NCHUNK (MOLA / CHUNK_MOL)     // 10
#define PAIR_THREADS 256

__global__ __launch_bounds__(PAIR_THREADS)
void pairs_kernel(float* __restrict__ out_mu, float* __restrict__ out_sig)
{
    __shared__ float4 sPmu[PROA * 2];   // 16 KB
    __shared__ float4 sPsg[PROA * 2];   // 16 KB
    __shared__ float4 sAmu[CHUNK_MOL * 2];
    __shared__ float4 sAsg[CHUNK_MOL * 2];
    __shared__ float  swarp[PAIR_THREADS / 32][HEADS];

    const int b     = blockIdx.x / NCHUNK;
    const int chunk = blockIdx.x % NCHUNK;
    const int tid   = threadIdx.x;
    const int sel   = tid & 1;
    const int wid   = tid >> 5;
    const int lid   = tid & 31;
    const int mbase = b * MOLA + chunk * CHUNK_MOL;

    // Stage P-tables (dense float4 copy) and the 5 A-term rows.
    {
        const float4* gPm = (const float4*)(g_Pmu  + (size_t)b * PROA * HEADS);
        const float4* gPs = (const float4*)(g_Psig + (size_t)b * PROA * HEADS);
        #pragma unroll
        for (int v = tid; v < PROA * 2; v += PAIR_THREADS) {
            sPmu[v] = gPm[v];
            sPsg[v] = gPs[v];
        }
        if (tid < CHUNK_MOL * 2) {
            sAmu[tid] = ((const float4*)g_Amu )[(size_t)mbase * 2 + tid];
            sAsg[tid] = ((const float4*)g_Asig)[(size_t)mbase * 2 + tid];
        }
    }
    __syncthreads();

    #pragma unroll 1
    for (int ma = 0; ma < CHUNK_MOL; ma++) {
        const int m = mbase + ma;
        const float4 a4 = sAmu[ma * 2 + sel];
        const float4 s4 = sAsg[ma * 2 + sel];

        float acc0 = 0.f, acc1 = 0.f, acc2 = 0.f, acc3 = 0.f;

        const size_t obase = (size_t)m * (PROA * 2);   // float4 index base
        float4* __restrict__ om = (float4*)out_mu  + obase;
        float4* __restrict__ os = (float4*)out_sig + obase;

        #pragma unroll
        for (int it = 0; it < (PROA * 2 + PAIR_THREADS - 1) / PAIR_THREADS; it++) {
            const int v = it * PAIR_THREADS + tid;
            if (v < PROA * 2) {
                const float4 pm = sPmu[v];
                const float4 ps = sPsg[v];

                const float xm0 = a4.x + pm.x, xm1 = a4.y + pm.y;
                const float xm2 = a4.z + pm.z, xm3 = a4.w + pm.w;
                const float xs0 = s4.x + ps.x, xs1 = s4.y + ps.y;
                const float xs2 = s4.z + ps.z, xs3 = s4.w + ps.w;

                const float mu0 = fmaxf(xm0 + 1.0f, __expf(fminf(xm0, 0.f)));
                const float mu1 = fmaxf(xm1 + 1.0f, __expf(fminf(xm1, 0.f)));
                const float mu2 = fmaxf(xm2 + 1.0f, __expf(fminf(xm2, 0.f)));
                const float mu3 = fmaxf(xm3 + 1.0f, __expf(fminf(xm3, 0.f)));
                const float sg0 = fmaxf(xs0 + 1.1f, __expf(fminf(xs0, 0.f)) + 0.1f);
                const float sg1 = fmaxf(xs1 + 1.1f, __expf(fminf(xs1, 0.f)) + 0.1f);
                const float sg2 = fmaxf(xs2 + 1.1f, __expf(fminf(xs2, 0.f)) + 0.1f);
                const float sg3 = fmaxf(xs3 + 1.1f, __expf(fminf(xs3, 0.f)) + 0.1f);

                acc0 += mu0; acc1 += mu1; acc2 += mu2; acc3 += mu3;

                __stcs(om + v, make_float4(mu0, mu1, mu2, mu3));
                __stcs(os + v, make_float4(sg0, sg1, sg2, sg3));
            }
        }

        // Deterministic reduction. Same-parity butterfly (16,8,4,2):
        // lane 0 -> heads 0-3 over even lanes, lane 1 -> heads 4-7 over odd.
        #pragma unroll
        for (int s = 16; s > 1; s >>= 1) {
            acc0 += __shfl_xor_sync(0xFFFFFFFFu, acc0, s);
            acc1 += __shfl_xor_sync(0xFFFFFFFFu, acc1, s);
            acc2 += __shfl_xor_sync(0xFFFFFFFFu, acc2, s);
            acc3 += __shfl_xor_sync(0xFFFFFFFFu, acc3, s);
        }
        if (lid < 2) {
            swarp[wid][lid * 4 + 0] = acc0;
            swarp[wid][lid * 4 + 1] = acc1;
            swarp[wid][lid * 4 + 2] = acc2;
            swarp[wid][lid * 4 + 3] = acc3;
        }
        __syncthreads();
        if (tid < HEADS) {
            float tsum = 0.f;
            #pragma unroll
            for (int w = 0; w < PAIR_THREADS / 32; w++) tsum += swarp[w][tid];
            g_ymol[(size_t)m * HEADS + tid] = tsum;
        }
        __syncthreads();   // protect swarp reuse next ma
    }
}

// ---------------------------------------------------------------------------
// Kernel 3: batch head.  y[b] = elu((0.001*sum_mol ymol) @ W1 + b1) @ W2 + b2
// Phase 1: 512 threads (b,h) sum the 50 mol atoms; phase 2: 64 threads MLP.
// ---------------------------------------------------------------------------
__global__ __launch_bounds__(512)
void final_kernel(const float* __restrict__ W1, const float* __restrict__ b1,
                  const float* __restrict__ W2, const float* __restrict__ b2,
                  float* __restrict__ out_y)
{
    __shared__ float sy[BATCH][HEADS];
    const int tid = threadIdx.x;
    {
        const int b = tid >> 3;
        const int h = tid & 7;
        float acc = 0.f;
        #pragma unroll 5
        for (int m = 0; m < MOLA; m++)
            acc += g_ymol[((size_t)b * MOLA + m) * HEADS + h];
        sy[b][h] = acc * 0.001f;
    }
    __syncthreads();
    if (tid < BATCH) {
        const int b = tid;
        float y[HEADS];
        #pragma unroll
        for (int h = 0; h < HEADS; h++) y[h] = sy[b][h];
        float outv = b2[0];
        #pragma unroll
        for (int j = 0; j < 2 * HEADS; j++) {
            float t = b1[j];
            #pragma unroll
            for (int h = 0; h < HEADS; h++)
                t = fmaf(y[h], W1[h * (2 * HEADS) + j], t);
            t = (t > 0.f) ? t : expm1f(t);           // plain elu, keep precise
            outv = fmaf(t, W2[j], outv);
        }
        out_y[b] = outv;
    }
}

// ---------------------------------------------------------------------------
// Launch. Inputs (metadata order): mol_feats, pro_feats, spatial_feats,
// W_sigma, b_sigma, W_mu, b_mu, W1, b1, W2, b2, mol_index, pro_index, mol_batch.
// Indices are fully structured -> computed arithmetically, never read.
// Output: [mu (P*8) | sigma (P*8) | y (64)] float32.
// ---------------------------------------------------------------------------
extern "C" void kernel_launch(void* const* d_in, const int* in_sizes, int n_in,
                              void* d_out, int out_size)
{
    const float* mol_feats = (const float*)d_in[0];
    const float* pro_feats = (const float*)d_in[1];
    const float* spat      = (const float*)d_in[2];
    const float* Wsig      = (const float*)d_in[3];
    const float* bsig      = (const float*)d_in[4];
    const float* Wmu       = (const float*)d_in[5];
    const float* bmu       = (const float*)d_in[6];
    const float* W1        = (const float*)d_in[7];
    const float* b1        = (const float*)d_in[8];
    const float* W2        = (const float*)d_in[9];
    const float* b2        = (const float*)d_in[10];

    float* out_mu  = (float*)d_out;
    float* out_sig = out_mu + NPAIR * HEADS;
    float* out_y   = out_mu + 2 * NPAIR * HEADS;

    const int threadsTot = (NMOL + NPRO) * 8;            // 281,600 (exact blocks)
    proj_kernel<<<threadsTot / 256, 256>>>(mol_feats, pro_feats, spat,
                                           Wsig, bsig, Wmu, bmu);
    pairs_kernel<<<BATCH * NCHUNK, PAIR_THREADS>>>(out_mu, out_sig);
    final_kernel<<<1, 512>>>(W1, b1, W2, b2, out_y);
}

// round 12
// speedup vs baseline: 2.1793x; 1.2319x over previous
#include <cuda_runtime.h>
#include <math.h>

#define BATCH 64
#define MOLA  50
#define PROA  500
#define HID   32
#define HEADS 8
#define NMOL  (BATCH * MOLA)          // 3200
#define NPRO  (BATCH * PROA)          // 32000
#define NPAIR ((size_t)NMOL * PROA)   // 1,600,000

// Scratch (allocation-free rule: __device__ globals)
__device__ float g_Amu [NMOL * HEADS];
__device__ float g_Asig[NMOL * HEADS];
__device__ float g_Pmu [NPRO * HEADS];
__device__ float g_Psig[NPRO * HEADS];
__device__ float g_ymol[NMOL * HEADS];

// ---------------------------------------------------------------------------
// Kernel 1: per-atom projections, staged two-phase design.
// Block = 256 rows. Blocks 0..124: pro rows (125*256 = 32,000 exact).
// Blocks 125..137: mol rows (13*256 = 3328 >= 3200, tail guarded).
// Phase A: dense coalesced float4 loads of feats (and spat for pro; product
//          fused) into transposed smem tile sF[c][row] (c = k-chunk 0..7).
//          16 independent LDG.128 per thread, every instruction 512B dense.
// Phase B: thread -> (row, head-half); 8 LDS.128 (conflict <= 2-way) + 8-chain
//          FMA; dense float4 stores (lane stride 16B).
// ---------------------------------------------------------------------------
#define PROJ_ROWS 256
#define PRO_BLOCKS (NPRO / PROJ_ROWS)         // 125

__global__ __launch_bounds__(256)
void proj_kernel(const float* __restrict__ mol_feats,
                 const float* __restrict__ pro_feats,
                 const float* __restrict__ spat,
                 const float* __restrict__ Wsig,
                 const float* __restrict__ bsig,
                 const float* __restrict__ Wmu,
                 const float* __restrict__ bmu)
{
    __shared__ float4 sWmu4[2 * HID * 2];     // [k][half], 2 KB
    __shared__ float4 sWsg4[2 * HID * 2];
    __shared__ float4 sF[8][PROJ_ROWS + 4];   // [c][row], ~33 KB

    const int tid = threadIdx.x;
    if (tid < 128) sWmu4[tid] = ((const float4*)Wmu)[tid];
    else           sWsg4[tid - 128] = ((const float4*)Wsig)[tid - 128];
    if (tid < 128) sWsg4[tid + 0] = ((const float4*)Wsig)[tid];   // fill rest
    else           sWmu4[tid - 128 + 0] = sWmu4[tid - 128];       // no-op pattern
    // (simpler + correct: just load both fully)
    __syncthreads();
    if (tid < 128) { sWmu4[tid] = ((const float4*)Wmu)[tid];
                     sWsg4[tid] = ((const float4*)Wsig)[tid]; }
    __syncthreads();

    const bool proBlock = (blockIdx.x < PRO_BLOCKS);
    const int  rbase    = proBlock ? blockIdx.x * PROJ_ROWS
                                   : (blockIdx.x - PRO_BLOCKS) * PROJ_ROWS;
    const int  nvalid   = proBlock ? PROJ_ROWS
                                   : ((NMOL - rbase) < PROJ_ROWS ? (NMOL - rbase)
                                                                 : PROJ_ROWS);

    // --- Phase A: stage feats (x spat) products, dense + transposed ---
    {
        const float4* f4p = proBlock ? (const float4*)(pro_feats + (size_t)rbase * HID)
                                     : (const float4*)(mol_feats + (size_t)rbase * HID);
        const float4* s4p = (const float4*)(spat + (size_t)rbase * HID);
        const int nval4 = nvalid * 8;
        #pragma unroll
        for (int i = 0; i < 8; i++) {
            const int v  = tid + 256 * i;
            const int vc = (v < nval4) ? v : 0;
            float4 f4 = f4p[vc];
            if (proBlock) {
                const float4 s4 = s4p[vc];
                f4.x *= s4.x; f4.y *= s4.y; f4.z *= s4.z; f4.w *= s4.w;
            }
            sF[v & 7][v >> 3] = f4;
        }
    }
    __syncthreads();

    // --- Phase B: compute (row, half) projections ---
    const int wbase = proBlock ? HID : 0;
    #pragma unroll 1
    for (int iter = 0; iter < 2; iter++) {
        const int rl   = iter * 128 + (tid >> 1);   // local row
        const int half = tid & 1;

        float a0, a1, a2, a3, c0, c1, c2, c3;
        if (proBlock) { a0=a1=a2=a3=c0=c1=c2=c3=0.f; }
        else {
            const float4 bm = ((const float4*)bmu)[half];
            const float4 bs = ((const float4*)bsig)[half];
            a0=bm.x; a1=bm.y; a2=bm.z; a3=bm.w;
            c0=bs.x; c1=bs.y; c2=bs.z; c3=bs.w;
        }

        #pragma unroll
        for (int c = 0; c < 8; c++) {
            const float4 f4 = sF[c][rl];
            const float fv[4] = { f4.x, f4.y, f4.z, f4.w };
            #pragma unroll
            for (int e = 0; e < 4; e++) {
                const int k = c * 4 + e;
                const float4 wm = sWmu4[(wbase + k) * 2 + half];
                const float4 ws = sWsg4[(wbase + k) * 2 + half];
                a0 = fmaf(fv[e], wm.x, a0); a1 = fmaf(fv[e], wm.y, a1);
                a2 = fmaf(fv[e], wm.z, a2); a3 = fmaf(fv[e], wm.w, a3);
                c0 = fmaf(fv[e], ws.x, c0); c1 = fmaf(fv[e], ws.y, c1);
                c2 = fmaf(fv[e], ws.z, c2); c3 = fmaf(fv[e], ws.w, c3);
            }
        }

        if (rl < nvalid) {
            const size_t idx = (size_t)(rbase + rl) * 2 + half;  // float4 index
            if (proBlock) {
                ((float4*)g_Pmu )[idx] = make_float4(a0, a1, a2, a3);
                ((float4*)g_Psig)[idx] = make_float4(c0, c1, c2, c3);
            } else {
                ((float4*)g_Amu )[idx] = make_float4(a0, a1, a2, a3);
                ((float4*)g_Asig)[idx] = make_float4(c0, c1, c2, c3);
            }
        }
    }
}

// ---------------------------------------------------------------------------
// Kernel 2 (proven R9/R11 structure, unchanged): per-pair mu/sigma +
// per-mol-atom sum of mu. Block = (complex, chunk of 5 mol atoms): 640 x 256.
// Work item v = q*2 + sel: 16B lane stride -> fully dense STG.128, streaming.
// Branchless ELU: mu = max(x+1, exp(min(x,0))), sg = max(x+1.1, exp(min(x,0))+0.1)
// ---------------------------------------------------------------------------
#define CHUNK_MOL 5
#define NCHUNK (MOLA / CHUNK_MOL)     // 10
#define PAIR_THREADS 256

__global__ __launch_bounds__(PAIR_THREADS)
void pairs_kernel(float* __restrict__ out_mu, float* __restrict__ out_sig)
{
    __shared__ float4 sPmu[PROA * 2];   // 16 KB
    __shared__ float4 sPsg[PROA * 2];   // 16 KB
    __shared__ float4 sAmu[CHUNK_MOL * 2];
    __shared__ float4 sAsg[CHUNK_MOL * 2];
    __shared__ float  swarp[PAIR_THREADS / 32][HEADS];

    const int b     = blockIdx.x / NCHUNK;
    const int chunk = blockIdx.x % NCHUNK;
    const int tid   = threadIdx.x;
    const int sel   = tid & 1;
    const int wid   = tid >> 5;
    const int lid   = tid & 31;
    const int mbase = b * MOLA + chunk * CHUNK_MOL;

    {
        const float4* gPm = (const float4*)(g_Pmu  + (size_t)b * PROA * HEADS);
        const float4* gPs = (const float4*)(g_Psig + (size_t)b * PROA * HEADS);
        #pragma unroll
        for (int v = tid; v < PROA * 2; v += PAIR_THREADS) {
            sPmu[v] = gPm[v];
            sPsg[v] = gPs[v];
        }
        if (tid < CHUNK_MOL * 2) {
            sAmu[tid] = ((const float4*)g_Amu )[(size_t)mbase * 2 + tid];
            sAsg[tid] = ((const float4*)g_Asig)[(size_t)mbase * 2 + tid];
        }
    }
    __syncthreads();

    #pragma unroll 1
    for (int ma = 0; ma < CHUNK_MOL; ma++) {
        const int m = mbase + ma;
        const float4 a4 = sAmu[ma * 2 + sel];
        const float4 s4 = sAsg[ma * 2 + sel];

        float acc0 = 0.f, acc1 = 0.f, acc2 = 0.f, acc3 = 0.f;

        const size_t obase = (size_t)m * (PROA * 2);   // float4 index base
        float4* __restrict__ om = (float4*)out_mu  + obase;
        float4* __restrict__ os = (float4*)out_sig + obase;

        #pragma unroll
        for (int it = 0; it < (PROA * 2 + PAIR_THREADS - 1) / PAIR_THREADS; it++) {
            const int v = it * PAIR_THREADS + tid;
            if (v < PROA * 2) {
                const float4 pm = sPmu[v];
                const float4 ps = sPsg[v];

                const float xm0 = a4.x + pm.x, xm1 = a4.y + pm.y;
                const float xm2 = a4.z + pm.z, xm3 = a4.w + pm.w;
                const float xs0 = s4.x + ps.x, xs1 = s4.y + ps.y;
                const float xs2 = s4.z + ps.z, xs3 = s4.w + ps.w;

                const float mu0 = fmaxf(xm0 + 1.0f, __expf(fminf(xm0, 0.f)));
                const float mu1 = fmaxf(xm1 + 1.0f, __expf(fminf(xm1, 0.f)));
                const float mu2 = fmaxf(xm2 + 1.0f, __expf(fminf(xm2, 0.f)));
                const float mu3 = fmaxf(xm3 + 1.0f, __expf(fminf(xm3, 0.f)));
                const float sg0 = fmaxf(xs0 + 1.1f, __expf(fminf(xs0, 0.f)) + 0.1f);
                const float sg1 = fmaxf(xs1 + 1.1f, __expf(fminf(xs1, 0.f)) + 0.1f);
                const float sg2 = fmaxf(xs2 + 1.1f, __expf(fminf(xs2, 0.f)) + 0.1f);
                const float sg3 = fmaxf(xs3 + 1.1f, __expf(fminf(xs3, 0.f)) + 0.1f);

                acc0 += mu0; acc1 += mu1; acc2 += mu2; acc3 += mu3;

                __stcs(om + v, make_float4(mu0, mu1, mu2, mu3));
                __stcs(os + v, make_float4(sg0, sg1, sg2, sg3));
            }
        }

        #pragma unroll
        for (int s = 16; s > 1; s >>= 1) {
            acc0 += __shfl_xor_sync(0xFFFFFFFFu, acc0, s);
            acc1 += __shfl_xor_sync(0xFFFFFFFFu, acc1, s);
            acc2 += __shfl_xor_sync(0xFFFFFFFFu, acc2, s);
            acc3 += __shfl_xor_sync(0xFFFFFFFFu, acc3, s);
        }
        if (lid < 2) {
            swarp[wid][lid * 4 + 0] = acc0;
            swarp[wid][lid * 4 + 1] = acc1;
            swarp[wid][lid * 4 + 2] = acc2;
            swarp[wid][lid * 4 + 3] = acc3;
        }
        __syncthreads();
        if (tid < HEADS) {
            float tsum = 0.f;
            #pragma unroll
            for (int w = 0; w < PAIR_THREADS / 32; w++) tsum += swarp[w][tid];
            g_ymol[(size_t)m * HEADS + tid] = tsum;
        }
        __syncthreads();
    }
}

// ---------------------------------------------------------------------------
// Kernel 3: batch head.  y[b] = elu((0.001*sum_mol ymol) @ W1 + b1) @ W2 + b2
// ---------------------------------------------------------------------------
__global__ __launch_bounds__(512)
void final_kernel(const float* __restrict__ W1, const float* __restrict__ b1,
                  const float* __restrict__ W2, const float* __restrict__ b2,
                  float* __restrict__ out_y)
{
    __shared__ float sy[BATCH][HEADS];
    const int tid = threadIdx.x;
    {
        const int b = tid >> 3;
        const int h = tid & 7;
        float acc = 0.f;
        #pragma unroll 5
        for (int m = 0; m < MOLA; m++)
            acc += g_ymol[((size_t)b * MOLA + m) * HEADS + h];
        sy[b][h] = acc * 0.001f;
    }
    __syncthreads();
    if (tid < BATCH) {
        const int b = tid;
        float y[HEADS];
        #pragma unroll
        for (int h = 0; h < HEADS; h++) y[h] = sy[b][h];
        float outv = b2[0];
        #pragma unroll
        for (int j = 0; j < 2 * HEADS; j++) {
            float t = b1[j];
            #pragma unroll
            for (int h = 0; h < HEADS; h++)
                t = fmaf(y[h], W1[h * (2 * HEADS) + j], t);
            t = (t > 0.f) ? t : expm1f(t);           // plain elu, keep precise
            outv = fmaf(t, W2[j], outv);
        }
        out_y[b] = outv;
    }
}

// ---------------------------------------------------------------------------
// Launch. Inputs (metadata order): mol_feats, pro_feats, spatial_feats,
// W_sigma, b_sigma, W_mu, b_mu, W1, b1, W2, b2, mol_index, pro_index, mol_batch.
// Indices are fully structured -> computed arithmetically, never read.
// Output: [mu (P*8) | sigma (P*8) | y (64)] float32.
// ---------------------------------------------------------------------------
extern "C" void kernel_launch(void* const* d_in, const int* in_sizes, int n_in,
                              void* d_out, int out_size)
{
    const float* mol_feats = (const float*)d_in[0];
    const float* pro_feats = (const float*)d_in[1];
    const float* spat      = (const float*)d_in[2];
    const float* Wsig      = (const float*)d_in[3];
    const float* bsig      = (const float*)d_in[4];
    const float* Wmu       = (const float*)d_in[5];
    const float* bmu       = (const float*)d_in[6];
    const float* W1        = (const float*)d_in[7];
    const float* b1        = (const float*)d_in[8];
    const float* W2        = (const float*)d_in[9];
    const float* b2        = (const float*)d_in[10];

    float* out_mu  = (float*)d_out;
    float* out_sig = out_mu + NPAIR * HEADS;
    float* out_y   = out_mu + 2 * NPAIR * HEADS;

    const int molBlocks = (NMOL + PROJ_ROWS - 1) / PROJ_ROWS;   // 13
    proj_kernel<<<PRO_BLOCKS + molBlocks, 256>>>(mol_feats, pro_feats, spat,
                                                 Wsig, bsig, Wmu, bmu);
    pairs_kernel<<<BATCH * NCHUNK, PAIR_THREADS>>>(out_mu, out_sig);
    final_kernel<<<1, 512>>>(W1, b1, W2, b2, out_y);
}